// round 15
// baseline (speedup 1.0000x reference)
#include <cuda_runtime.h>
#include <cuda_fp16.h>
#include <cstdint>

#define DIM   768
#define NH    12
#define HD    64
#define NTOK  16384
#define QKVN  2304

// ---- scratch (static __device__, allocation-free) ----
__device__ uint32_t g_a1[(size_t)NTOK * DIM];    // sorted, masked, tf32 input
__device__ __half   g_qkv[(size_t)NTOK * QKVN];  // sorted qkv (fp16 storage)
__device__ uint32_t g_a3[(size_t)NTOK * DIM];    // sorted attn out (tf32)
__device__ uint32_t g_w1[(size_t)QKVN * DIM];    // qkv_w tf32
__device__ uint32_t g_w3[(size_t)DIM * DIM];     // proj_w tf32
__device__ int g_perm[NTOK];
__device__ int g_esort[NTOK];
__device__ int g_cnt[4];
__device__ int g_pos[4];

__device__ __forceinline__ uint32_t f2tf32(float f) {
    uint32_t u;
    asm("cvt.rna.tf32.f32 %0, %1;" : "=r"(u) : "f"(f));
    return u;
}

__device__ __forceinline__ void mma_tf32(float c[4], const uint32_t a[4], const uint32_t b[2]) {
    asm volatile(
        "mma.sync.aligned.m16n8k8.row.col.f32.tf32.tf32.f32 "
        "{%0,%1,%2,%3}, {%4,%5,%6,%7}, {%8,%9}, {%0,%1,%2,%3};\n"
        : "+f"(c[0]), "+f"(c[1]), "+f"(c[2]), "+f"(c[3])
        : "r"(a[0]), "r"(a[1]), "r"(a[2]), "r"(a[3]), "r"(b[0]), "r"(b[1]));
}

__device__ __forceinline__ void cp16(uint32_t* dst, const void* src) {
    uint32_t d = (uint32_t)__cvta_generic_to_shared(dst);
    asm volatile("cp.async.cg.shared.global [%0], [%1], 16;\n" :: "r"(d), "l"(src));
}

// ---------- expert counting sort ----------
__global__ void sort_count(const int* __restrict__ e) {
    __shared__ int h[4];
    if (threadIdx.x < 4) h[threadIdx.x] = 0;
    __syncthreads();
    for (int i = blockIdx.x * blockDim.x + threadIdx.x; i < NTOK; i += gridDim.x * blockDim.x)
        atomicAdd(&h[e[i]], 1);
    __syncthreads();
    if (threadIdx.x < 4) atomicAdd(&g_cnt[threadIdx.x], h[threadIdx.x]);
}

__global__ void sort_prefix() {
    if (threadIdx.x == 0) {
        int b = 0;
        for (int ex = 0; ex < 4; ex++) { g_pos[ex] = b; b += g_cnt[ex]; }
    }
}

// ---------- fused scatter + gather + mask + tf32-convert ----------
__global__ __launch_bounds__(192)
void prep_x(const float* __restrict__ x, const int* __restrict__ e) {
    __shared__ int sp, sex;
    const int i = blockIdx.x;
    if (threadIdx.x == 0) {
        const int ex = e[i];
        const int p = atomicAdd(&g_pos[ex], 1);
        g_perm[p] = i;
        g_esort[p] = ex;
        sp = p; sex = ex;
    }
    __syncthreads();
    const int p  = sp;
    const int de = 96 << sex;
    const int c  = threadIdx.x * 4;
    float4 v = *(const float4*)(x + (size_t)i * DIM + c);
    uint4 o;
    if (c < de) {
        o.x = f2tf32(v.x); o.y = f2tf32(v.y); o.z = f2tf32(v.z); o.w = f2tf32(v.w);
    } else {
        o.x = o.y = o.z = o.w = 0u;
    }
    *(uint4*)(g_a1 + (size_t)p * DIM + c) = o;
}

// one launch converts both weight matrices
#define W1_QUADS (QKVN * DIM / 4)   // 442368
#define W3_QUADS (DIM * DIM / 4)    // 147456
__global__ void prep_w2(const float* __restrict__ w1, const float* __restrict__ w3) {
    const int i = blockIdx.x * blockDim.x + threadIdx.x;
    const float4* src;
    uint4* dst;
    int idx;
    if (i < W1_QUADS) {
        src = (const float4*)w1; dst = (uint4*)g_w1; idx = i;
    } else {
        src = (const float4*)w3; dst = (uint4*)g_w3; idx = i - W1_QUADS;
    }
    float4 v = src[idx];
    uint4 o;
    o.x = f2tf32(v.x); o.y = f2tf32(v.y); o.z = f2tf32(v.z); o.w = f2tf32(v.w);
    dst[idx] = o;
}

// ---------- pipelined tf32 GEMM: C[M,N] = A[M,K=768] @ W[N,K]^T ----------
// 128x128 CTA tile, 4 warps, 64x64 warp tile, 3-stage cp.async pipeline
// (R10 loop: prefetch distance 3, wait_group NSTG-1, two syncs per K-iter —
//  empirically faster than the single-sync distance-2 variant, R12).
// MODE 0: qkv — K-loop bounded by tile kmax (sorted nesting), fp16 store (Ch)
// MODE 1: proj — zero-skip N-tiles, bias + nested output mask, row scatter (C)
#define NSTG 3

template<int MODE>
__global__ __launch_bounds__(128)
void gemm_pipe(const uint32_t* __restrict__ A, const uint32_t* __restrict__ W,
               __half* __restrict__ Ch, float* __restrict__ C,
               const float* __restrict__ bias, int N)
{
    extern __shared__ uint32_t sh[];   // A: s*4096 | B: 12288 + s*4096

    const int tid   = threadIdx.x;
    const int warp  = tid >> 5;
    const int lane  = tid & 31;
    const int warpM = warp >> 1;   // 0..1
    const int warpN = warp & 1;    // 0..1
    const int m0 = blockIdx.y * 128;
    const int n0 = blockIdx.x * 128;
    const int gr = lane >> 2;      // 0..7
    const int tc = lane & 3;       // 0..3
    const int lr = tid >> 3;       // 0..15
    const int lc = (tid & 7) << 2; // 0..28 step 4
    const int K = DIM;

    const int demax = 96 << g_esort[m0 + 127];   // sorted ascending -> tile max

    if (MODE == 1 && n0 >= demax) {
        const int orow = g_perm[m0 + tid];
        const float4 z = make_float4(0.f, 0.f, 0.f, 0.f);
#pragma unroll
        for (int c = 0; c < 128; c += 4)
            *(float4*)(C + (size_t)orow * N + n0 + c) = z;
        return;
    }

    const int nk = (MODE == 0) ? (demax >> 5) : (DIM >> 5);   // >= 3 always

    auto load_stage = [&](int s, int kb) {
#pragma unroll
        for (int rr = 0; rr < 8; rr++) {
            const int row = rr * 16 + lr;
            const int sw = (((lc >> 2) ^ (row & 7)) << 2);
            cp16(sh + s * 4096 + row * 32 + sw,         A + (size_t)(m0 + row) * K + kb + lc);
            cp16(sh + 12288 + s * 4096 + row * 32 + sw, W + (size_t)(n0 + row) * K + kb + lc);
        }
    };

    float acc[4][8][4];
#pragma unroll
    for (int i = 0; i < 4; i++)
#pragma unroll
        for (int j = 0; j < 8; j++)
#pragma unroll
            for (int r = 0; r < 4; r++) acc[i][j][r] = 0.0f;

#pragma unroll
    for (int s = 0; s < NSTG; s++) {
        load_stage(s, s * 32);
        asm volatile("cp.async.commit_group;\n");
    }

    for (int t = 0; t < nk; t++) {
        const int s = t % NSTG;
        asm volatile("cp.async.wait_group %0;\n" :: "n"(NSTG - 1));
        __syncthreads();

        const uint32_t* as = sh + s * 4096;
        const uint32_t* bs = sh + 12288 + s * 4096;
#pragma unroll
        for (int kk = 0; kk < 32; kk += 8) {
            const int ch0 = (((kk >> 2)     ) ^ gr) << 2;
            const int ch1 = (((kk >> 2) + 1) ^ gr) << 2;
            uint32_t af[4][4], bf[8][2];
#pragma unroll
            for (int i = 0; i < 4; i++) {
                const int r0 = (warpM * 64 + i * 16 + gr) * 32 + tc;
                af[i][0] = as[r0 + ch0];
                af[i][1] = as[r0 + 256 + ch0];
                af[i][2] = as[r0 + ch1];
                af[i][3] = as[r0 + 256 + ch1];
            }
#pragma unroll
            for (int j = 0; j < 8; j++) {
                const int r = (warpN * 64 + j * 8 + gr) * 32 + tc;
                bf[j][0] = bs[r + ch0];
                bf[j][1] = bs[r + ch1];
            }
#pragma unroll
            for (int i = 0; i < 4; i++)
#pragma unroll
                for (int j = 0; j < 8; j++)
                    mma_tf32(acc[i][j], af[i], bf[j]);
        }
        __syncthreads();

        if (t + NSTG < nk) load_stage(s, (t + NSTG) * 32);
        asm volatile("cp.async.commit_group;\n");   // uniform group count
    }

    // epilogue
#pragma unroll
    for (int i = 0; i < 4; i++) {
#pragma unroll
        for (int half = 0; half < 2; half++) {
            const int rs = m0 + warpM * 64 + i * 16 + gr + half * 8;  // sorted row
            int orow = rs, de = 0;
            if (MODE == 1) { orow = g_perm[rs]; de = 96 << g_esort[rs]; }
#pragma unroll
            for (int j = 0; j < 8; j++) {
                const int c = n0 + warpN * 64 + j * 8 + tc * 2;
                float v0 = acc[i][j][half * 2 + 0];
                float v1 = acc[i][j][half * 2 + 1];
                if (MODE == 1) {
                    v0 += bias[c];
                    v1 += bias[c + 1];
                    v0 = (c     < de) ? v0 : 0.0f;
                    v1 = (c + 1 < de) ? v1 : 0.0f;
                    *(float2*)(C + (size_t)orow * N + c) = make_float2(v0, v1);
                } else {
                    *(__half2*)(Ch + (size_t)orow * N + c) = __floats2half2_rn(v0, v1);
                }
            }
        }
    }
}

// ---------- per-token attention over heads ----------
// 16 lanes per token (2 tokens/warp, 8/CTA). q/k/v fp16 in smem (stride 68),
// scores fp32. Smem/CTA = 43.8KB -> ~5 CTAs/SM.
#define TOKB 5472   // bytes/token: qkv 3*12*68*2 = 4896 | sc 144*4 = 576
__global__ __launch_bounds__(128)
void attn_kernel()
{
    extern __shared__ char smc[];   // 8 * TOKB bytes
    const int warp = threadIdx.x >> 5;
    const int lane = threadIdx.x & 31;
    const int hw   = lane >> 4;
    const int l16  = lane & 15;
    const int tok  = blockIdx.x * 8 + warp * 2 + hw;

    __half* hq = (__half*)(smc + (warp * 2 + hw) * TOKB);
    __half* hk = hq + 12 * 68;
    __half* hv = hq + 24 * 68;
    float*  sc = (float*)(hq + 36 * 68);

    const __half* qp = g_qkv + (size_t)tok * QKVN;
    for (int i = l16; i < QKVN / 4; i += 16) {
        const uint2 u = *(const uint2*)(qp + i * 4);
        const int w0  = i * 4;
        const int reg = w0 / DIM;
        const int rem = w0 - reg * DIM;
        const int row = rem >> 6;
        const int e   = rem & 63;
        *(uint2*)(hq + reg * 816 + row * 68 + e) = u;
    }
    __syncwarp();

    const int l0 = (l16 >> 2) * 3;
    const int s0 = (l16 & 3) * 3;
    float d00 = 0, d01 = 0, d02 = 0, d10 = 0, d11 = 0, d12 = 0, d20 = 0, d21 = 0, d22 = 0;
#pragma unroll 8
    for (int e = 0; e < 64; e += 2) {
        const float2 q0 = __half22float2(*(const __half2*)(hq + (l0    ) * 68 + e));
        const float2 q1 = __half22float2(*(const __half2*)(hq + (l0 + 1) * 68 + e));
        const float2 q2 = __half22float2(*(const __half2*)(hq + (l0 + 2) * 68 + e));
        const float2 k0 = __half22float2(*(const __half2*)(hk + (s0    ) * 68 + e));
        const float2 k1 = __half22float2(*(const __half2*)(hk + (s0 + 1) * 68 + e));
        const float2 k2 = __half22float2(*(const __half2*)(hk + (s0 + 2) * 68 + e));
        d00 += q0.x * k0.x + q0.y * k0.y;
        d01 += q0.x * k1.x + q0.y * k1.y;
        d02 += q0.x * k2.x + q0.y * k2.y;
        d10 += q1.x * k0.x + q1.y * k0.y;
        d11 += q1.x * k1.x + q1.y * k1.y;
        d12 += q1.x * k2.x + q1.y * k2.y;
        d20 += q2.x * k0.x + q2.y * k0.y;
        d21 += q2.x * k1.x + q2.y * k1.y;
        d22 += q2.x * k2.x + q2.y * k2.y;
    }
    sc[(l0    ) * 12 + s0    ] = d00 * 0.125f;
    sc[(l0    ) * 12 + s0 + 1] = d01 * 0.125f;
    sc[(l0    ) * 12 + s0 + 2] = d02 * 0.125f;
    sc[(l0 + 1) * 12 + s0    ] = d10 * 0.125f;
    sc[(l0 + 1) * 12 + s0 + 1] = d11 * 0.125f;
    sc[(l0 + 1) * 12 + s0 + 2] = d12 * 0.125f;
    sc[(l0 + 2) * 12 + s0    ] = d20 * 0.125f;
    sc[(l0 + 2) * 12 + s0 + 1] = d21 * 0.125f;
    sc[(l0 + 2) * 12 + s0 + 2] = d22 * 0.125f;
    __syncwarp();

    if (l16 < 12) {
        float m = -1e30f;
#pragma unroll
        for (int s2 = 0; s2 < 12; s2++) m = fmaxf(m, sc[l16 * 12 + s2]);
        float sum = 0.0f;
#pragma unroll
        for (int s2 = 0; s2 < 12; s2++) {
            const float ex = __expf(sc[l16 * 12 + s2] - m);
            sc[l16 * 12 + s2] = ex;
            sum += ex;
        }
        const float inv = 1.0f / sum;
#pragma unroll
        for (int s2 = 0; s2 < 12; s2++) sc[l16 * 12 + s2] *= inv;
    }
    __syncwarp();

    const int e0 = l16 * 4;
    float vv[12][4];
#pragma unroll
    for (int s2 = 0; s2 < 12; s2++) {
        const float2 a = __half22float2(*(const __half2*)(hv + s2 * 68 + e0));
        const float2 b = __half22float2(*(const __half2*)(hv + s2 * 68 + e0 + 2));
        vv[s2][0] = a.x; vv[s2][1] = a.y; vv[s2][2] = b.x; vv[s2][3] = b.y;
    }
    uint32_t* op = g_a3 + (size_t)tok * DIM;
#pragma unroll
    for (int l = 0; l < 12; l++) {
        float a0 = 0, a1 = 0, a2 = 0, a3 = 0;
#pragma unroll
        for (int s2 = 0; s2 < 12; s2++) {
            const float w = sc[l * 12 + s2];
            a0 += w * vv[s2][0];
            a1 += w * vv[s2][1];
            a2 += w * vv[s2][2];
            a3 += w * vv[s2][3];
        }
        uint4 o;
        o.x = f2tf32(a0); o.y = f2tf32(a1); o.z = f2tf32(a2); o.w = f2tf32(a3);
        *(uint4*)(op + l * 64 + e0) = o;
    }
}

extern "C" void kernel_launch(void* const* d_in, const int* in_sizes, int n_in,
                              void* d_out, int out_size)
{
    const float* x      = (const float*)d_in[0];
    const int*   expert = (const int*)  d_in[1];
    const float* qkv_w  = (const float*)d_in[2];
    const float* proj_w = (const float*)d_in[3];
    const float* proj_b = (const float*)d_in[4];
    float* out = (float*)d_out;

    void *p_cnt, *p_a1, *p_qkv, *p_a3, *p_w1, *p_w3;
    cudaGetSymbolAddress(&p_cnt, g_cnt);
    cudaGetSymbolAddress(&p_a1,  g_a1);
    cudaGetSymbolAddress(&p_qkv, g_qkv);
    cudaGetSymbolAddress(&p_a3,  g_a3);
    cudaGetSymbolAddress(&p_w1,  g_w1);
    cudaGetSymbolAddress(&p_w3,  g_w3);

    const int GSMEM = 2 * NSTG * 4096 * 4;   // 98304
    const int ASMEM = 8 * TOKB;              // 43776
    cudaFuncSetAttribute(gemm_pipe<0>, cudaFuncAttributeMaxDynamicSharedMemorySize, GSMEM);
    cudaFuncSetAttribute(gemm_pipe<1>, cudaFuncAttributeMaxDynamicSharedMemorySize, GSMEM);
    cudaFuncSetAttribute(attn_kernel,  cudaFuncAttributeMaxDynamicSharedMemorySize, ASMEM);

    // launch order puts gemm_pipe<0> at index 6 so ncu (-s 5 -c 1) profiles it
    // 1) expert histogram + prefix                          (launches 1-3)
    cudaMemsetAsync(p_cnt, 0, 4 * sizeof(int));
    sort_count<<<64, 256>>>(expert);
    sort_prefix<<<1, 32>>>();

    // 2) fused scatter/gather/mask/convert + single weight-convert (4-5)
    prep_x<<<NTOK, 192>>>(x, expert);
    prep_w2<<<(W1_QUADS + W3_QUADS) / 256, 256>>>(qkv_w, proj_w);

    // 3) qkv GEMM (K bounded per tile by nested width, fp16 store)  (6)
    gemm_pipe<0><<<dim3(QKVN / 128, NTOK / 128), 128, GSMEM>>>(
        (const uint32_t*)p_a1, (const uint32_t*)p_w1, (__half*)p_qkv, nullptr, nullptr, QKVN);

    // 4) per-token head attention                                   (7)
    attn_kernel<<<NTOK / 8, 128, ASMEM>>>();

    // 5) proj GEMM (N-tile skip + bias + nested mask + row scatter) (8)
    gemm_pipe<1><<<dim3(DIM / 128, NTOK / 128), 128, GSMEM>>>(
        (const uint32_t*)p_a3, (const uint32_t*)p_w3, nullptr, out, proj_b, DIM);
}

// round 17
// speedup vs baseline: 1.0062x; 1.0062x over previous
#include <cuda_runtime.h>
#include <cuda_fp16.h>
#include <cstdint>

#define DIM   768
#define NH    12
#define HD    64
#define NTOK  16384
#define QKVN  2304

// ---- scratch (static __device__, allocation-free) ----
__device__ uint32_t g_a1[(size_t)NTOK * DIM];    // sorted, masked, tf32 input
__device__ __half   g_qkv[(size_t)NTOK * QKVN];  // sorted qkv (fp16 storage)
__device__ uint32_t g_a3[(size_t)NTOK * DIM];    // sorted attn out (tf32)
__device__ uint32_t g_w1[(size_t)QKVN * DIM];    // qkv_w tf32
__device__ uint32_t g_w3[(size_t)DIM * DIM];     // proj_w tf32
__device__ int g_perm[NTOK];
__device__ int g_esort[NTOK];
__device__ int g_cnt[4];
__device__ int g_pos[4];

__device__ __forceinline__ uint32_t f2tf32(float f) {
    uint32_t u;
    asm("cvt.rna.tf32.f32 %0, %1;" : "=r"(u) : "f"(f));
    return u;
}

__device__ __forceinline__ void mma_tf32(float c[4], const uint32_t a[4], const uint32_t b[2]) {
    asm volatile(
        "mma.sync.aligned.m16n8k8.row.col.f32.tf32.tf32.f32 "
        "{%0,%1,%2,%3}, {%4,%5,%6,%7}, {%8,%9}, {%0,%1,%2,%3};\n"
        : "+f"(c[0]), "+f"(c[1]), "+f"(c[2]), "+f"(c[3])
        : "r"(a[0]), "r"(a[1]), "r"(a[2]), "r"(a[3]), "r"(b[0]), "r"(b[1]));
}

__device__ __forceinline__ void cp16(uint32_t* dst, const void* src) {
    uint32_t d = (uint32_t)__cvta_generic_to_shared(dst);
    asm volatile("cp.async.cg.shared.global [%0], [%1], 16;\n" :: "r"(d), "l"(src));
}

// ---------- expert counting sort ----------
__global__ void sort_count(const int* __restrict__ e) {
    __shared__ int h[4];
    if (threadIdx.x < 4) h[threadIdx.x] = 0;
    __syncthreads();
    for (int i = blockIdx.x * blockDim.x + threadIdx.x; i < NTOK; i += gridDim.x * blockDim.x)
        atomicAdd(&h[e[i]], 1);
    __syncthreads();
    if (threadIdx.x < 4) atomicAdd(&g_cnt[threadIdx.x], h[threadIdx.x]);
}

__global__ void sort_prefix() {
    if (threadIdx.x == 0) {
        int b = 0;
        for (int ex = 0; ex < 4; ex++) { g_pos[ex] = b; b += g_cnt[ex]; }
    }
}

// ---------- fused scatter + gather + mask + tf32-convert + weight convert ----
// One block per ORIGINAL token. Threads 128..163 of block b additionally
// convert weight quad b*36 + (t-128); 16384*36 = 589824 covers w1+w3 exactly.
#define W1_QUADS (QKVN * DIM / 4)              // 442368
#define W3_QUADS (DIM * DIM / 4)               // 147456
#define WT_QUADS (W1_QUADS + W3_QUADS)         // 589824 = NTOK*36
__global__ __launch_bounds__(192)
void prep_xw(const float* __restrict__ x, const int* __restrict__ e,
             const float* __restrict__ w1, const float* __restrict__ w3) {
    __shared__ int sp, sex;
    const int i = blockIdx.x;
    if (threadIdx.x == 0) {
        const int ex = e[i];
        const int p = atomicAdd(&g_pos[ex], 1);
        g_perm[p] = i;
        g_esort[p] = ex;
        sp = p; sex = ex;
    }
    // weight slice on threads 128..163 (disjoint from the thread-0 atomic)
    if (threadIdx.x >= 128 && threadIdx.x < 164) {
        const int q = i * 36 + (threadIdx.x - 128);
        const float4* src;
        uint4* dst;
        int idx;
        if (q < W1_QUADS) {
            src = (const float4*)w1; dst = (uint4*)g_w1; idx = q;
        } else {
            src = (const float4*)w3; dst = (uint4*)g_w3; idx = q - W1_QUADS;
        }
        float4 v = src[idx];
        uint4 o;
        o.x = f2tf32(v.x); o.y = f2tf32(v.y); o.z = f2tf32(v.z); o.w = f2tf32(v.w);
        dst[idx] = o;
    }
    __syncthreads();
    const int p  = sp;
    const int de = 96 << sex;
    const int c  = threadIdx.x * 4;
    float4 v = *(const float4*)(x + (size_t)i * DIM + c);
    uint4 o;
    if (c < de) {
        o.x = f2tf32(v.x); o.y = f2tf32(v.y); o.z = f2tf32(v.z); o.w = f2tf32(v.w);
    } else {
        o.x = o.y = o.z = o.w = 0u;
    }
    *(uint4*)(g_a1 + (size_t)p * DIM + c) = o;
}

// ---------- pipelined tf32 GEMM: C[M,N] = A[M,K=768] @ W[N,K]^T ----------
// 128x128 CTA tile, 4 warps, 64x64 warp tile, 3-stage cp.async pipeline
// (R10 loop: prefetch distance 3, wait_group NSTG-1, two syncs per K-iter).
// MODE 0: qkv — K-loop bounded by tile kmax (sorted nesting), fp16 store (Ch)
// MODE 1: proj — zero-skip N-tiles, bias + nested output mask, row scatter (C)
#define NSTG 3

template<int MODE>
__global__ __launch_bounds__(128)
void gemm_pipe(const uint32_t* __restrict__ A, const uint32_t* __restrict__ W,
               __half* __restrict__ Ch, float* __restrict__ C,
               const float* __restrict__ bias, int N)
{
    extern __shared__ uint32_t sh[];   // A: s*4096 | B: 12288 + s*4096

    const int tid   = threadIdx.x;
    const int warp  = tid >> 5;
    const int lane  = tid & 31;
    const int warpM = warp >> 1;   // 0..1
    const int warpN = warp & 1;    // 0..1
    const int m0 = blockIdx.y * 128;
    const int n0 = blockIdx.x * 128;
    const int gr = lane >> 2;      // 0..7
    const int tc = lane & 3;       // 0..3
    const int lr = tid >> 3;       // 0..15
    const int lc = (tid & 7) << 2; // 0..28 step 4
    const int K = DIM;

    const int demax = 96 << g_esort[m0 + 127];   // sorted ascending -> tile max

    if (MODE == 1 && n0 >= demax) {
        const int orow = g_perm[m0 + tid];
        const float4 z = make_float4(0.f, 0.f, 0.f, 0.f);
#pragma unroll
        for (int c = 0; c < 128; c += 4)
            *(float4*)(C + (size_t)orow * N + n0 + c) = z;
        return;
    }

    const int nk = (MODE == 0) ? (demax >> 5) : (DIM >> 5);   // >= 3 always

    auto load_stage = [&](int s, int kb) {
#pragma unroll
        for (int rr = 0; rr < 8; rr++) {
            const int row = rr * 16 + lr;
            const int sw = (((lc >> 2) ^ (row & 7)) << 2);
            cp16(sh + s * 4096 + row * 32 + sw,         A + (size_t)(m0 + row) * K + kb + lc);
            cp16(sh + 12288 + s * 4096 + row * 32 + sw, W + (size_t)(n0 + row) * K + kb + lc);
        }
    };

    float acc[4][8][4];
#pragma unroll
    for (int i = 0; i < 4; i++)
#pragma unroll
        for (int j = 0; j < 8; j++)
#pragma unroll
            for (int r = 0; r < 4; r++) acc[i][j][r] = 0.0f;

#pragma unroll
    for (int s = 0; s < NSTG; s++) {
        load_stage(s, s * 32);
        asm volatile("cp.async.commit_group;\n");
    }

    for (int t = 0; t < nk; t++) {
        const int s = t % NSTG;
        asm volatile("cp.async.wait_group %0;\n" :: "n"(NSTG - 1));
        __syncthreads();

        const uint32_t* as = sh + s * 4096;
        const uint32_t* bs = sh + 12288 + s * 4096;
#pragma unroll
        for (int kk = 0; kk < 32; kk += 8) {
            const int ch0 = (((kk >> 2)     ) ^ gr) << 2;
            const int ch1 = (((kk >> 2) + 1) ^ gr) << 2;
            uint32_t af[4][4], bf[8][2];
#pragma unroll
            for (int i = 0; i < 4; i++) {
                const int r0 = (warpM * 64 + i * 16 + gr) * 32 + tc;
                af[i][0] = as[r0 + ch0];
                af[i][1] = as[r0 + 256 + ch0];
                af[i][2] = as[r0 + ch1];
                af[i][3] = as[r0 + 256 + ch1];
            }
#pragma unroll
            for (int j = 0; j < 8; j++) {
                const int r = (warpN * 64 + j * 8 + gr) * 32 + tc;
                bf[j][0] = bs[r + ch0];
                bf[j][1] = bs[r + ch1];
            }
#pragma unroll
            for (int i = 0; i < 4; i++)
#pragma unroll
                for (int j = 0; j < 8; j++)
                    mma_tf32(acc[i][j], af[i], bf[j]);
        }
        __syncthreads();

        if (t + NSTG < nk) load_stage(s, (t + NSTG) * 32);
        asm volatile("cp.async.commit_group;\n");   // uniform group count
    }

    // epilogue
#pragma unroll
    for (int i = 0; i < 4; i++) {
#pragma unroll
        for (int half = 0; half < 2; half++) {
            const int rs = m0 + warpM * 64 + i * 16 + gr + half * 8;  // sorted row
            int orow = rs, de = 0;
            if (MODE == 1) { orow = g_perm[rs]; de = 96 << g_esort[rs]; }
#pragma unroll
            for (int j = 0; j < 8; j++) {
                const int c = n0 + warpN * 64 + j * 8 + tc * 2;
                float v0 = acc[i][j][half * 2 + 0];
                float v1 = acc[i][j][half * 2 + 1];
                if (MODE == 1) {
                    v0 += bias[c];
                    v1 += bias[c + 1];
                    v0 = (c     < de) ? v0 : 0.0f;
                    v1 = (c + 1 < de) ? v1 : 0.0f;
                    *(float2*)(C + (size_t)orow * N + c) = make_float2(v0, v1);
                } else {
                    *(__half2*)(Ch + (size_t)orow * N + c) = __floats2half2_rn(v0, v1);
                }
            }
        }
    }
}

// ---------- per-token attention over heads ----------
// 16 lanes per token (2 tokens/warp, 8/CTA). q/k/v fp16 in smem (stride 68),
// scores fp32. Smem/CTA = 43.8KB -> ~5 CTAs/SM.
#define TOKB 5472   // bytes/token: qkv 3*12*68*2 = 4896 | sc 144*4 = 576
__global__ __launch_bounds__(128)
void attn_kernel()
{
    extern __shared__ char smc[];   // 8 * TOKB bytes
    const int warp = threadIdx.x >> 5;
    const int lane = threadIdx.x & 31;
    const int hw   = lane >> 4;
    const int l16  = lane & 15;
    const int tok  = blockIdx.x * 8 + warp * 2 + hw;

    __half* hq = (__half*)(smc + (warp * 2 + hw) * TOKB);
    __half* hk = hq + 12 * 68;
    __half* hv = hq + 24 * 68;
    float*  sc = (float*)(hq + 36 * 68);

    const __half* qp = g_qkv + (size_t)tok * QKVN;
    for (int i = l16; i < QKVN / 4; i += 16) {
        const uint2 u = *(const uint2*)(qp + i * 4);
        const int w0  = i * 4;
        const int reg = w0 / DIM;
        const int rem = w0 - reg * DIM;
        const int row = rem >> 6;
        const int e   = rem & 63;
        *(uint2*)(hq + reg * 816 + row * 68 + e) = u;
    }
    __syncwarp();

    const int l0 = (l16 >> 2) * 3;
    const int s0 = (l16 & 3) * 3;
    float d00 = 0, d01 = 0, d02 = 0, d10 = 0, d11 = 0, d12 = 0, d20 = 0, d21 = 0, d22 = 0;
#pragma unroll 8
    for (int e = 0; e < 64; e += 2) {
        const float2 q0 = __half22float2(*(const __half2*)(hq + (l0    ) * 68 + e));
        const float2 q1 = __half22float2(*(const __half2*)(hq + (l0 + 1) * 68 + e));
        const float2 q2 = __half22float2(*(const __half2*)(hq + (l0 + 2) * 68 + e));
        const float2 k0 = __half22float2(*(const __half2*)(hk + (s0    ) * 68 + e));
        const float2 k1 = __half22float2(*(const __half2*)(hk + (s0 + 1) * 68 + e));
        const float2 k2 = __half22float2(*(const __half2*)(hk + (s0 + 2) * 68 + e));
        d00 += q0.x * k0.x + q0.y * k0.y;
        d01 += q0.x * k1.x + q0.y * k1.y;
        d02 += q0.x * k2.x + q0.y * k2.y;
        d10 += q1.x * k0.x + q1.y * k0.y;
        d11 += q1.x * k1.x + q1.y * k1.y;
        d12 += q1.x * k2.x + q1.y * k2.y;
        d20 += q2.x * k0.x + q2.y * k0.y;
        d21 += q2.x * k1.x + q2.y * k1.y;
        d22 += q2.x * k2.x + q2.y * k2.y;
    }
    sc[(l0    ) * 12 + s0    ] = d00 * 0.125f;
    sc[(l0    ) * 12 + s0 + 1] = d01 * 0.125f;
    sc[(l0    ) * 12 + s0 + 2] = d02 * 0.125f;
    sc[(l0 + 1) * 12 + s0    ] = d10 * 0.125f;
    sc[(l0 + 1) * 12 + s0 + 1] = d11 * 0.125f;
    sc[(l0 + 1) * 12 + s0 + 2] = d12 * 0.125f;
    sc[(l0 + 2) * 12 + s0    ] = d20 * 0.125f;
    sc[(l0 + 2) * 12 + s0 + 1] = d21 * 0.125f;
    sc[(l0 + 2) * 12 + s0 + 2] = d22 * 0.125f;
    __syncwarp();

    if (l16 < 12) {
        float m = -1e30f;
#pragma unroll
        for (int s2 = 0; s2 < 12; s2++) m = fmaxf(m, sc[l16 * 12 + s2]);
        float sum = 0.0f;
#pragma unroll
        for (int s2 = 0; s2 < 12; s2++) {
            const float ex = __expf(sc[l16 * 12 + s2] - m);
            sc[l16 * 12 + s2] = ex;
            sum += ex;
        }
        const float inv = 1.0f / sum;
#pragma unroll
        for (int s2 = 0; s2 < 12; s2++) sc[l16 * 12 + s2] *= inv;
    }
    __syncwarp();

    const int e0 = l16 * 4;
    float vv[12][4];
#pragma unroll
    for (int s2 = 0; s2 < 12; s2++) {
        const float2 a = __half22float2(*(const __half2*)(hv + s2 * 68 + e0));
        const float2 b = __half22float2(*(const __half2*)(hv + s2 * 68 + e0 + 2));
        vv[s2][0] = a.x; vv[s2][1] = a.y; vv[s2][2] = b.x; vv[s2][3] = b.y;
    }
    uint32_t* op = g_a3 + (size_t)tok * DIM;
#pragma unroll
    for (int l = 0; l < 12; l++) {
        float a0 = 0, a1 = 0, a2 = 0, a3 = 0;
#pragma unroll
        for (int s2 = 0; s2 < 12; s2++) {
            const float w = sc[l * 12 + s2];
            a0 += w * vv[s2][0];
            a1 += w * vv[s2][1];
            a2 += w * vv[s2][2];
            a3 += w * vv[s2][3];
        }
        uint4 o;
        o.x = f2tf32(a0); o.y = f2tf32(a1); o.z = f2tf32(a2); o.w = f2tf32(a3);
        *(uint4*)(op + l * 64 + e0) = o;
    }
}

extern "C" void kernel_launch(void* const* d_in, const int* in_sizes, int n_in,
                              void* d_out, int out_size)
{
    const float* x      = (const float*)d_in[0];
    const int*   expert = (const int*)  d_in[1];
    const float* qkv_w  = (const float*)d_in[2];
    const float* proj_w = (const float*)d_in[3];
    const float* proj_b = (const float*)d_in[4];
    float* out = (float*)d_out;

    void *p_cnt, *p_a1, *p_qkv, *p_a3, *p_w1, *p_w3;
    cudaGetSymbolAddress(&p_cnt, g_cnt);
    cudaGetSymbolAddress(&p_a1,  g_a1);
    cudaGetSymbolAddress(&p_qkv, g_qkv);
    cudaGetSymbolAddress(&p_a3,  g_a3);
    cudaGetSymbolAddress(&p_w1,  g_w1);
    cudaGetSymbolAddress(&p_w3,  g_w3);

    const int GSMEM = 2 * NSTG * 4096 * 4;   // 98304
    const int ASMEM = 8 * TOKB;              // 43776
    cudaFuncSetAttribute(gemm_pipe<0>, cudaFuncAttributeMaxDynamicSharedMemorySize, GSMEM);
    cudaFuncSetAttribute(gemm_pipe<1>, cudaFuncAttributeMaxDynamicSharedMemorySize, GSMEM);
    cudaFuncSetAttribute(attn_kernel,  cudaFuncAttributeMaxDynamicSharedMemorySize, ASMEM);

    // kernel-launch order (0-based): sort_count 0, sort_prefix 1, prep_xw 2,
    // gemm1 3  <- ncu capture lands on index 3 (empirical across R2..R15)
    cudaMemsetAsync(p_cnt, 0, 4 * sizeof(int));
    sort_count<<<64, 256>>>(expert);
    sort_prefix<<<1, 32>>>();
    prep_xw<<<NTOK, 192>>>(x, expert, qkv_w, proj_w);

    gemm_pipe<0><<<dim3(QKVN / 128, NTOK / 128), 128, GSMEM>>>(
        (const uint32_t*)p_a1, (const uint32_t*)p_w1, (__half*)p_qkv, nullptr, nullptr, QKVN);

    attn_kernel<<<NTOK / 8, 128, ASMEM>>>();

    gemm_pipe<1><<<dim3(DIM / 128, NTOK / 128), 128, GSMEM>>>(
        (const uint32_t*)p_a3, (const uint32_t*)p_w3, nullptr, out, proj_b, DIM);
}